// round 1
// baseline (speedup 1.0000x reference)
#include <cuda_runtime.h>
#include <cuda_bf16.h>
#include <cstddef>

// Problem constants: B=8, T=1024, C=768, H=12, d=64
//   QKV:  x[8192,768] @ w_attn[768,2304] + b  -> q,k,v  [B,H,1024,64]
//   attn: causal flash, scores = (q*0.125) . (k + rel_shift)^T
//   proj: y[8192,768] @ w_proj[768,768] + b -> out

#define ELEMS_BHTD (8 * 12 * 1024 * 64)   // 6291456
#define ELEMS_BTC  (8 * 1024 * 768)       // 6291456

static __device__ float g_q[ELEMS_BHTD];
static __device__ float g_k[ELEMS_BHTD];
static __device__ float g_v[ELEMS_BHTD];
static __device__ float g_y[ELEMS_BTC];

// ---------------------------------------------------------------------------
// Tiled SGEMM: C[M,N] = A[M,K] @ B[K,N] (+bias), 128x128 tile, BK=16,
// 256 threads, 8x8 micro-tile per thread.
// EPI==0: QKV epilogue (scatter into g_q/g_k/g_v with scale / rel bias)
// EPI==1: plain epilogue, A taken from g_y, writes Cout
// ---------------------------------------------------------------------------
template <int EPI>
__global__ void __launch_bounds__(256) sgemm128(
    const float* __restrict__ A, const float* __restrict__ Bw,
    const float* __restrict__ bias, const float* __restrict__ rel,
    float* __restrict__ Cout, const int N, const int K)
{
    __shared__ float As[16][128];   // transposed A tile: As[k][m]
    __shared__ float Bs[16][128];   // Bs[k][n]

    const int tid  = threadIdx.x;
    const int tx   = tid & 15;      // 16 col groups
    const int ty   = tid >> 4;      // 16 row groups
    const int arow = tid >> 2;      // 0..63
    const int acol = (tid & 3) << 2;
    const int brow = tid >> 5;      // 0..7
    const int bcol = (tid & 31) << 2;

    const float* Ap   = (EPI == 1) ? g_y : A;
    const float* Ablk = Ap + (size_t)blockIdx.y * 128 * K;
    const float* Bblk = Bw + blockIdx.x * 128;

    float acc[8][8];
#pragma unroll
    for (int i = 0; i < 8; i++)
#pragma unroll
        for (int j = 0; j < 8; j++) acc[i][j] = 0.0f;

    for (int k0 = 0; k0 < K; k0 += 16) {
        float4 a0 = *(const float4*)(Ablk + (size_t)arow * K + k0 + acol);
        float4 a1 = *(const float4*)(Ablk + (size_t)(arow + 64) * K + k0 + acol);
        float4 b0 = *(const float4*)(Bblk + (size_t)(k0 + brow) * N + bcol);
        float4 b1 = *(const float4*)(Bblk + (size_t)(k0 + brow + 8) * N + bcol);

        As[acol + 0][arow] = a0.x; As[acol + 1][arow] = a0.y;
        As[acol + 2][arow] = a0.z; As[acol + 3][arow] = a0.w;
        As[acol + 0][arow + 64] = a1.x; As[acol + 1][arow + 64] = a1.y;
        As[acol + 2][arow + 64] = a1.z; As[acol + 3][arow + 64] = a1.w;
        *(float4*)&Bs[brow][bcol]     = b0;
        *(float4*)&Bs[brow + 8][bcol] = b1;
        __syncthreads();

#pragma unroll
        for (int kk = 0; kk < 16; kk++) {
            float a[8], b[8];
            *(float4*)&a[0] = *(const float4*)&As[kk][ty * 8];
            *(float4*)&a[4] = *(const float4*)&As[kk][ty * 8 + 4];
            *(float4*)&b[0] = *(const float4*)&Bs[kk][tx * 8];
            *(float4*)&b[4] = *(const float4*)&Bs[kk][tx * 8 + 4];
#pragma unroll
            for (int i = 0; i < 8; i++)
#pragma unroll
                for (int j = 0; j < 8; j++)
                    acc[i][j] = fmaf(a[i], b[j], acc[i][j]);
        }
        __syncthreads();
    }

    // Epilogue
#pragma unroll
    for (int i = 0; i < 8; i++) {
        const int m = blockIdx.y * 128 + ty * 8 + i;
#pragma unroll
        for (int j = 0; j < 8; j++) {
            const int n = blockIdx.x * 128 + tx * 8 + j;
            float val = acc[i][j] + bias[n];
            if (EPI == 0) {
                const int which = n / 768;            // 0=q, 1=k, 2=v
                const int ch = n - which * 768;
                const int hh = ch >> 6;
                const int dd = ch & 63;
                const int bb = m >> 10;
                const int t  = m & 1023;
                const size_t idx = ((((size_t)bb * 12 + hh) << 10) + t) * 64 + dd;
                if (which == 0) {
                    g_q[idx] = val * 0.125f;          // d^-0.5, d=64
                } else if (which == 1) {
                    float rb = (t > 0) ? rel[(size_t)(t - 1) * 64 + dd] : 0.0f;
                    g_k[idx] = val + rb;              // fold rel bias into K
                } else {
                    g_v[idx] = val;
                }
            } else {
                Cout[(size_t)m * N + n] = val;
            }
        }
    }
}

// ---------------------------------------------------------------------------
// Flash attention, fp32. Per block: 64 queries x full causal K range of one
// (b,h). 64x64 tiles; smem: Q^T, K^T (reused as P^T), V. 256 threads,
// thread (ty,tx) owns a 4x4 micro-tile.
// ---------------------------------------------------------------------------
__global__ void __launch_bounds__(256) flash_kernel()
{
    __shared__ float Qt[64][64];    // Qt[d][i]
    __shared__ float KPt[64][64];   // Kt[d][j], reused as Pt[j][i]
    __shared__ float Vs[64][64];    // Vs[j][d]

    const int qt  = blockIdx.x;     // query tile 0..15
    const int bh  = blockIdx.y;     // 0..95
    const int tid = threadIdx.x;
    const int tx  = tid & 15;
    const int ty  = tid >> 4;

    const float* qp = g_q + (size_t)bh * 65536;
    const float* kp = g_k + (size_t)bh * 65536;
    const float* vp = g_v + (size_t)bh * 65536;
    const int q0 = qt * 64;

    // Load Q tile transposed
#pragma unroll
    for (int it = 0; it < 4; it++) {
        const int idx = tid + it * 256;
        const int row = idx >> 4;
        const int dg  = (idx & 15) << 2;
        float4 v = *(const float4*)(qp + (size_t)(q0 + row) * 64 + dg);
        Qt[dg + 0][row] = v.x; Qt[dg + 1][row] = v.y;
        Qt[dg + 2][row] = v.z; Qt[dg + 3][row] = v.w;
    }

    float O[4][4] = {};
    float mrow[4] = {-1e30f, -1e30f, -1e30f, -1e30f};
    float lrow[4] = {0.0f, 0.0f, 0.0f, 0.0f};

    for (int kt = 0; kt <= qt; kt++) {
        __syncthreads();            // prev PV done / Q loaded before overwrite
        const int k0 = kt * 64;
#pragma unroll
        for (int it = 0; it < 4; it++) {
            const int idx = tid + it * 256;
            const int row = idx >> 4;
            const int dg  = (idx & 15) << 2;
            float4 kv = *(const float4*)(kp + (size_t)(k0 + row) * 64 + dg);
            KPt[dg + 0][row] = kv.x; KPt[dg + 1][row] = kv.y;
            KPt[dg + 2][row] = kv.z; KPt[dg + 3][row] = kv.w;
            *(float4*)&Vs[row][dg] = *(const float4*)(vp + (size_t)(k0 + row) * 64 + dg);
        }
        __syncthreads();

        // S = Q K^T (64x64x64)
        float s[4][4];
#pragma unroll
        for (int r = 0; r < 4; r++)
#pragma unroll
            for (int c = 0; c < 4; c++) s[r][c] = 0.0f;
#pragma unroll 16
        for (int kk = 0; kk < 64; kk++) {
            float qa[4], kb[4];
            *(float4*)qa = *(const float4*)&Qt[kk][ty * 4];
            *(float4*)kb = *(const float4*)&KPt[kk][tx * 4];
#pragma unroll
            for (int r = 0; r < 4; r++)
#pragma unroll
                for (int c = 0; c < 4; c++)
                    s[r][c] = fmaf(qa[r], kb[c], s[r][c]);
        }

        // Causal mask on the diagonal tile
        if (kt == qt) {
#pragma unroll
            for (int r = 0; r < 4; r++)
#pragma unroll
                for (int c = 0; c < 4; c++)
                    if (tx * 4 + c > ty * 4 + r) s[r][c] = -1e30f;
        }

        // Online softmax update (row-wise, reduce across tx = 16 lanes)
#pragma unroll
        for (int r = 0; r < 4; r++) {
            float mt = fmaxf(fmaxf(s[r][0], s[r][1]), fmaxf(s[r][2], s[r][3]));
#pragma unroll
            for (int off = 8; off > 0; off >>= 1)
                mt = fmaxf(mt, __shfl_xor_sync(0xffffffffu, mt, off));
            const float mnew = fmaxf(mrow[r], mt);
            const float fac  = __expf(mrow[r] - mnew);
            float sum = 0.0f;
#pragma unroll
            for (int c = 0; c < 4; c++) {
                s[r][c] = __expf(s[r][c] - mnew);
                sum += s[r][c];
            }
#pragma unroll
            for (int off = 8; off > 0; off >>= 1)
                sum += __shfl_xor_sync(0xffffffffu, sum, off);
            lrow[r] = lrow[r] * fac + sum;
            mrow[r] = mnew;
#pragma unroll
            for (int c = 0; c < 4; c++) O[r][c] *= fac;
        }

        // Write P^T into KPt (K no longer needed)
        __syncthreads();
#pragma unroll
        for (int r = 0; r < 4; r++)
#pragma unroll
            for (int c = 0; c < 4; c++)
                KPt[tx * 4 + c][ty * 4 + r] = s[r][c];
        __syncthreads();

        // O += P V (64x64x64)
#pragma unroll 16
        for (int kk = 0; kk < 64; kk++) {
            float pa[4], vb[4];
            *(float4*)pa = *(const float4*)&KPt[kk][ty * 4];
            *(float4*)vb = *(const float4*)&Vs[kk][tx * 4];
#pragma unroll
            for (int r = 0; r < 4; r++)
#pragma unroll
                for (int c = 0; c < 4; c++)
                    O[r][c] = fmaf(pa[r], vb[c], O[r][c]);
        }
    }

    // Epilogue: y[b][t][h*64+d] = O / l
    const int bb = bh / 12;
    const int hh = bh - bb * 12;
#pragma unroll
    for (int r = 0; r < 4; r++) {
        const float inv = 1.0f / lrow[r];
        const int t = q0 + ty * 4 + r;
        float4 o;
        o.x = O[r][0] * inv; o.y = O[r][1] * inv;
        o.z = O[r][2] * inv; o.w = O[r][3] * inv;
        *(float4*)(g_y + ((size_t)(bb * 1024 + t)) * 768 + hh * 64 + tx * 4) = o;
    }
}

// ---------------------------------------------------------------------------
extern "C" void kernel_launch(void* const* d_in, const int* in_sizes, int n_in,
                              void* d_out, int out_size)
{
    const float* x      = (const float*)d_in[0];
    const float* w_attn = (const float*)d_in[1];
    const float* b_attn = (const float*)d_in[2];
    const float* w_proj = (const float*)d_in[3];
    const float* b_proj = (const float*)d_in[4];
    const float* rel    = (const float*)d_in[5];
    float* out = (float*)d_out;

    (void)in_sizes; (void)n_in; (void)out_size;

    // 1) QKV GEMM + scatter epilogue (q scaled, k + rel bias)
    dim3 g1(2304 / 128, 8192 / 128);
    sgemm128<0><<<g1, 256>>>(x, w_attn, b_attn, rel, nullptr, 2304, 768);

    // 2) Flash causal attention -> g_y [B,T,C]
    flash_kernel<<<dim3(16, 96), 256>>>();

    // 3) Output projection
    dim3 g2(768 / 128, 8192 / 128);
    sgemm128<1><<<g2, 256>>>(nullptr, w_proj, b_proj, nullptr, out, 768, 768);
}

// round 4
// speedup vs baseline: 1.7173x; 1.7173x over previous
#include <cuda_runtime.h>
#include <cstdint>
#include <cstddef>

// B=8, T=1024, C=768, H=12, d=64
//   prep:  tf32-round x, w_attn, w_proj (RNA) into scratch
//   QKV :  mma.sync tf32 128x128 tiles  -> scatter q/k/v (+bias, q*0.125, k+rel)
//   attn:  fp32 flash (writes y pre-rounded to tf32)
//   proj:  mma.sync tf32 -> out (+bias)

#define ELEMS_BHTD (8 * 12 * 1024 * 64)
#define ELEMS_BTC  (8 * 1024 * 768)

static __device__ float g_q[ELEMS_BHTD];
static __device__ float g_k[ELEMS_BHTD];
static __device__ float g_v[ELEMS_BHTD];
static __device__ float g_y[ELEMS_BTC];
static __device__ float g_xr[ELEMS_BTC];
static __device__ float g_wr1[768 * 2304];
static __device__ float g_wr2[768 * 768];

// ---------------------------------------------------------------- helpers --
__device__ __forceinline__ float tf32r(float x) {
    float r; asm("cvt.rna.tf32.f32 %0, %1;" : "=f"(r) : "f"(x)); return r;
}
__device__ __forceinline__ uint32_t smem_u32(const void* p) {
    uint32_t a;
    asm("{ .reg .u64 t; cvta.to.shared.u64 t, %1; cvt.u32.u64 %0, t; }"
        : "=r"(a) : "l"(p));
    return a;
}
__device__ __forceinline__ void cp16(uint32_t s, const float* g) {
    asm volatile("cp.async.ca.shared.global [%0], [%1], 16;"
                 :: "r"(s), "l"(g) : "memory");
}
__device__ __forceinline__ void mma_tf32(float* c, const uint32_t* a, const uint32_t* b) {
    asm volatile(
        "mma.sync.aligned.m16n8k8.row.col.f32.tf32.tf32.f32 "
        "{%0,%1,%2,%3}, {%4,%5,%6,%7}, {%8,%9}, {%0,%1,%2,%3};"
        : "+f"(c[0]), "+f"(c[1]), "+f"(c[2]), "+f"(c[3])
        : "r"(a[0]), "r"(a[1]), "r"(a[2]), "r"(a[3]), "r"(b[0]), "r"(b[1]));
}

// ----------------------------------------------------------- prep rounding --
__global__ void __launch_bounds__(256) round_tf32(const float* __restrict__ in,
                                                  float* __restrict__ out, int n4) {
    int i = blockIdx.x * 256 + threadIdx.x;
    if (i < n4) {
        float4 v = ((const float4*)in)[i];
        v.x = tf32r(v.x); v.y = tf32r(v.y); v.z = tf32r(v.z); v.w = tf32r(v.w);
        ((float4*)out)[i] = v;
    }
}

// ------------------------------------------------------------ tf32 GEMM ----
// C[m,n] = A[m,:] . Bw[:,n] (+bias). A: [M x 768] row-major (pre-rounded),
// Bw: [768 x N] row-major (pre-rounded). Block 128x128, 4 warps of 64x64.
// EPI 0: scatter q/k/v.  EPI 1: Cout[m*768+n].
template <int EPI>
__global__ void __launch_bounds__(128) gemm_mma(
    const float* __restrict__ Am, const float* __restrict__ Bw,
    const float* __restrict__ bias, const float* __restrict__ rel,
    float* __restrict__ Cout, const int N)
{
    constexpr int K = 768;
    constexpr int NC = K / 32;          // 24 chunks of BK=32
    constexpr int ASTG = 128 * 36;      // padded A stage (floats)
    constexpr int BSTG = 32 * 132;      // padded B stage

    extern __shared__ float sh[];
    float* As = sh;                     // [2][128][36]
    float* Bs = sh + 2 * ASTG;          // [2][32][132]

    const int tid  = threadIdx.x;
    const int wid  = tid >> 5;
    const int lane = tid & 31;
    const int g    = lane >> 2;         // groupID
    const int tig  = lane & 3;          // thread in group
    const int wm   = (wid >> 1) * 64;
    const int wn   = (wid & 1) * 64;
    const int bx = blockIdx.x, by = blockIdx.y;

    const float* Ablk = Am + (size_t)by * 128 * K;
    const float* Bblk = Bw + bx * 128;
    const uint32_t sA = smem_u32(As);
    const uint32_t sB = smem_u32(Bs);

    auto issue = [&](int c, int s) {
        const float* Ag = Ablk + c * 32;
#pragma unroll
        for (int i = 0; i < 8; i++) {
            const int idx = i * 128 + tid;
            const int row = idx >> 3, c4 = idx & 7;
            cp16(sA + (uint32_t)(s * ASTG + row * 36 + c4 * 4) * 4,
                 Ag + (size_t)row * K + c4 * 4);
        }
        const float* Bg = Bblk + (size_t)c * 32 * N;
#pragma unroll
        for (int i = 0; i < 8; i++) {
            const int idx = i * 128 + tid;
            const int kr = idx >> 5, c4 = idx & 31;
            cp16(sB + (uint32_t)(s * BSTG + kr * 132 + c4 * 4) * 4,
                 Bg + (size_t)kr * N + c4 * 4);
        }
        asm volatile("cp.async.commit_group;" ::: "memory");
    };

    float acc[4][8][4];
#pragma unroll
    for (int mt = 0; mt < 4; mt++)
#pragma unroll
        for (int nt = 0; nt < 8; nt++)
#pragma unroll
            for (int r = 0; r < 4; r++) acc[mt][nt][r] = 0.0f;

    issue(0, 0);
    for (int c = 0; c < NC; c++) {
        const int s = c & 1;
        if (c + 1 < NC) {
            issue(c + 1, (c + 1) & 1);
            asm volatile("cp.async.wait_group 1;" ::: "memory");
        } else {
            asm volatile("cp.async.wait_group 0;" ::: "memory");
        }
        __syncthreads();

        const float* A0 = As + s * ASTG;
        const float* B0 = Bs + s * BSTG;
#pragma unroll
        for (int ks = 0; ks < 4; ks++) {
            uint32_t af[4][4];
#pragma unroll
            for (int mt = 0; mt < 4; mt++) {
                const float* ap = A0 + (wm + mt * 16 + g) * 36 + ks * 8 + tig;
                af[mt][0] = __float_as_uint(ap[0]);
                af[mt][1] = __float_as_uint(ap[8 * 36]);
                af[mt][2] = __float_as_uint(ap[4]);
                af[mt][3] = __float_as_uint(ap[8 * 36 + 4]);
            }
            uint32_t bf[8][2];
#pragma unroll
            for (int nt = 0; nt < 8; nt++) {
                const float* bp = B0 + (ks * 8 + tig) * 132 + wn + nt * 8 + g;
                bf[nt][0] = __float_as_uint(bp[0]);
                bf[nt][1] = __float_as_uint(bp[4 * 132]);
            }
#pragma unroll
            for (int mt = 0; mt < 4; mt++)
#pragma unroll
                for (int nt = 0; nt < 8; nt++)
                    mma_tf32(acc[mt][nt], af[mt], bf[nt]);
        }
        __syncthreads();
    }

    // ---- epilogue: thread holds (g,2tig),(g,2tig+1),(g+8,2tig),(g+8,2tig+1)
    const int nb = bx * 128 + wn;
    const int mb = by * 128 + wm;
    if (EPI == 0) {
        const int which = (bx * 128) / 768;         // uniform per block
        float* dst = (which == 0) ? g_q : (which == 1) ? g_k : g_v;
        const int bb = (by * 128) >> 10;            // uniform per block
#pragma unroll
        for (int nt = 0; nt < 8; nt++) {
            const int n  = nb + nt * 8 + 2 * tig;
            const int nc = n - which * 768;
            const int hh = nc >> 6, dd = nc & 63;
            const float bv0 = bias[n], bv1 = bias[n + 1];
            const size_t hbase = (((size_t)(bb * 12 + hh)) << 10);
#pragma unroll
            for (int mt = 0; mt < 4; mt++) {
#pragma unroll
                for (int hr = 0; hr < 2; hr++) {
                    const int m = mb + mt * 16 + g + hr * 8;
                    const int t = m & 1023;
                    float v0 = acc[mt][nt][hr * 2 + 0] + bv0;
                    float v1 = acc[mt][nt][hr * 2 + 1] + bv1;
                    if (which == 0) { v0 *= 0.125f; v1 *= 0.125f; }
                    else if (which == 1 && t > 0) {
                        v0 += rel[(size_t)(t - 1) * 64 + dd];
                        v1 += rel[(size_t)(t - 1) * 64 + dd + 1];
                    }
                    float2 o; o.x = v0; o.y = v1;
                    *(float2*)&dst[(hbase + t) * 64 + dd] = o;
                }
            }
        }
    } else {
#pragma unroll
        for (int nt = 0; nt < 8; nt++) {
            const int n = nb + nt * 8 + 2 * tig;
            const float bv0 = bias[n], bv1 = bias[n + 1];
#pragma unroll
            for (int mt = 0; mt < 4; mt++) {
#pragma unroll
                for (int hr = 0; hr < 2; hr++) {
                    const int m = mb + mt * 16 + g + hr * 8;
                    float2 o;
                    o.x = acc[mt][nt][hr * 2 + 0] + bv0;
                    o.y = acc[mt][nt][hr * 2 + 1] + bv1;
                    *(float2*)&Cout[(size_t)m * 768 + n] = o;
                }
            }
        }
    }
}

// ------------------------------------------------------- flash attention --
__global__ void __launch_bounds__(256) flash_kernel()
{
    __shared__ float Qt[64][64];
    __shared__ float KPt[64][64];
    __shared__ float Vs[64][64];

    const int qt  = blockIdx.x;
    const int bh  = blockIdx.y;
    const int tid = threadIdx.x;
    const int tx  = tid & 15;
    const int ty  = tid >> 4;

    const float* qp = g_q + (size_t)bh * 65536;
    const float* kp = g_k + (size_t)bh * 65536;
    const float* vp = g_v + (size_t)bh * 65536;
    const int q0 = qt * 64;

#pragma unroll
    for (int it = 0; it < 4; it++) {
        const int idx = tid + it * 256;
        const int row = idx >> 4;
        const int dg  = (idx & 15) << 2;
        float4 v = *(const float4*)(qp + (size_t)(q0 + row) * 64 + dg);
        Qt[dg + 0][row] = v.x; Qt[dg + 1][row] = v.y;
        Qt[dg + 2][row] = v.z; Qt[dg + 3][row] = v.w;
    }

    float O[4][4] = {};
    float mrow[4] = {-1e30f, -1e30f, -1e30f, -1e30f};
    float lrow[4] = {0.0f, 0.0f, 0.0f, 0.0f};

    for (int kt = 0; kt <= qt; kt++) {
        __syncthreads();
        const int k0 = kt * 64;
#pragma unroll
        for (int it = 0; it < 4; it++) {
            const int idx = tid + it * 256;
            const int row = idx >> 4;
            const int dg  = (idx & 15) << 2;
            float4 kv = *(const float4*)(kp + (size_t)(k0 + row) * 64 + dg);
            KPt[dg + 0][row] = kv.x; KPt[dg + 1][row] = kv.y;
            KPt[dg + 2][row] = kv.z; KPt[dg + 3][row] = kv.w;
            *(float4*)&Vs[row][dg] = *(const float4*)(vp + (size_t)(k0 + row) * 64 + dg);
        }
        __syncthreads();

        float s[4][4];
#pragma unroll
        for (int r = 0; r < 4; r++)
#pragma unroll
            for (int c = 0; c < 4; c++) s[r][c] = 0.0f;
#pragma unroll 16
        for (int kk = 0; kk < 64; kk++) {
            float qa[4], kb[4];
            *(float4*)qa = *(const float4*)&Qt[kk][ty * 4];
            *(float4*)kb = *(const float4*)&KPt[kk][tx * 4];
#pragma unroll
            for (int r = 0; r < 4; r++)
#pragma unroll
                for (int c = 0; c < 4; c++)
                    s[r][c] = fmaf(qa[r], kb[c], s[r][c]);
        }

        if (kt == qt) {
#pragma unroll
            for (int r = 0; r < 4; r++)
#pragma unroll
                for (int c = 0; c < 4; c++)
                    if (tx * 4 + c > ty * 4 + r) s[r][c] = -1e30f;
        }

#pragma unroll
        for (int r = 0; r < 4; r++) {
            float mt = fmaxf(fmaxf(s[r][0], s[r][1]), fmaxf(s[r][2], s[r][3]));
#pragma unroll
            for (int off = 8; off > 0; off >>= 1)
                mt = fmaxf(mt, __shfl_xor_sync(0xffffffffu, mt, off));
            const float mnew = fmaxf(mrow[r], mt);
            const float fac  = __expf(mrow[r] - mnew);
            float sum = 0.0f;
#pragma unroll
            for (int c = 0; c < 4; c++) {
                s[r][c] = __expf(s[r][c] - mnew);
                sum += s[r][c];
            }
#pragma unroll
            for (int off = 8; off > 0; off >>= 1)
                sum += __shfl_xor_sync(0xffffffffu, sum, off);
            lrow[r] = lrow[r] * fac + sum;
            mrow[r] = mnew;
#pragma unroll
            for (int c = 0; c < 4; c++) O[r][c] *= fac;
        }

        __syncthreads();
#pragma unroll
        for (int r = 0; r < 4; r++)
#pragma unroll
            for (int c = 0; c < 4; c++)
                KPt[tx * 4 + c][ty * 4 + r] = s[r][c];
        __syncthreads();

#pragma unroll 16
        for (int kk = 0; kk < 64; kk++) {
            float pa[4], vb[4];
            *(float4*)pa = *(const float4*)&KPt[kk][ty * 4];
            *(float4*)vb = *(const float4*)&Vs[kk][tx * 4];
#pragma unroll
            for (int r = 0; r < 4; r++)
#pragma unroll
                for (int c = 0; c < 4; c++)
                    O[r][c] = fmaf(pa[r], vb[c], O[r][c]);
        }
    }

    // y written pre-rounded to tf32 so proj GEMM needs no cvt
    const int bb = bh / 12;
    const int hh = bh - bb * 12;
#pragma unroll
    for (int r = 0; r < 4; r++) {
        const float inv = 1.0f / lrow[r];
        const int t = q0 + ty * 4 + r;
        float4 o;
        o.x = tf32r(O[r][0] * inv); o.y = tf32r(O[r][1] * inv);
        o.z = tf32r(O[r][2] * inv); o.w = tf32r(O[r][3] * inv);
        *(float4*)(g_y + ((size_t)(bb * 1024 + t)) * 768 + hh * 64 + tx * 4) = o;
    }
}

// ---------------------------------------------------------------------------
extern "C" void kernel_launch(void* const* d_in, const int* in_sizes, int n_in,
                              void* d_out, int out_size)
{
    const float* x      = (const float*)d_in[0];
    const float* w_attn = (const float*)d_in[1];
    const float* b_attn = (const float*)d_in[2];
    const float* w_proj = (const float*)d_in[3];
    const float* b_proj = (const float*)d_in[4];
    const float* rel    = (const float*)d_in[5];
    float* out = (float*)d_out;
    (void)in_sizes; (void)n_in; (void)out_size;

    float *xr, *wr1, *wr2, *yp;
    cudaGetSymbolAddress((void**)&xr,  g_xr);
    cudaGetSymbolAddress((void**)&wr1, g_wr1);
    cudaGetSymbolAddress((void**)&wr2, g_wr2);
    cudaGetSymbolAddress((void**)&yp,  g_y);

    const int SMEM = (2 * 128 * 36 + 2 * 32 * 132) * 4;  // 70656 B
    cudaFuncSetAttribute(gemm_mma<0>, cudaFuncAttributeMaxDynamicSharedMemorySize, SMEM);
    cudaFuncSetAttribute(gemm_mma<1>, cudaFuncAttributeMaxDynamicSharedMemorySize, SMEM);

    // prep: tf32-round operands
    round_tf32<<<ELEMS_BTC / 4 / 256, 256>>>(x, xr, ELEMS_BTC / 4);
    round_tf32<<<768 * 2304 / 4 / 256, 256>>>(w_attn, wr1, 768 * 2304 / 4);
    round_tf32<<<768 * 768 / 4 / 256, 256>>>(w_proj, wr2, 768 * 768 / 4);

    // QKV GEMM (tensor cores) -> q/k/v scatter
    gemm_mma<0><<<dim3(18, 64), 128, SMEM>>>(xr, wr1, b_attn, rel, nullptr, 2304);

    // flash causal attention -> g_y (tf32-rounded)
    flash_kernel<<<dim3(16, 96), 256>>>();

    // projection (tensor cores)
    gemm_mma<1><<<dim3(6, 64), 128, SMEM>>>(yp, wr2, b_proj, nullptr, out, 768);
}

// round 5
// speedup vs baseline: 3.2416x; 1.8876x over previous
#include <cuda_runtime.h>
#include <cstdint>
#include <cstddef>

// B=8, T=1024, C=768, H=12, d=64
//   prep:  tf32-round x, w_attn, w_proj (RNA) into scratch
//   QKV :  mma.sync tf32 -> scatter q/k/v as tf32 (+bias, q*0.125, k+rel)
//   attn:  tensor-core flash (tf32 mma for QK^T and PV), fp32 softmax
//   proj:  mma.sync tf32 -> out (+bias)

#define ELEMS_BHTD (8 * 12 * 1024 * 64)
#define ELEMS_BTC  (8 * 1024 * 768)

static __device__ float g_q[ELEMS_BHTD];
static __device__ float g_k[ELEMS_BHTD];
static __device__ float g_v[ELEMS_BHTD];
static __device__ float g_y[ELEMS_BTC];
static __device__ float g_xr[ELEMS_BTC];
static __device__ float g_wr1[768 * 2304];
static __device__ float g_wr2[768 * 768];

// ---------------------------------------------------------------- helpers --
__device__ __forceinline__ float tf32r(float x) {
    float r; asm("cvt.rna.tf32.f32 %0, %1;" : "=f"(r) : "f"(x)); return r;
}
__device__ __forceinline__ uint32_t smem_u32(const void* p) {
    uint32_t a;
    asm("{ .reg .u64 t; cvta.to.shared.u64 t, %1; cvt.u32.u64 %0, t; }"
        : "=r"(a) : "l"(p));
    return a;
}
__device__ __forceinline__ void cp16(uint32_t s, const float* g) {
    asm volatile("cp.async.ca.shared.global [%0], [%1], 16;"
                 :: "r"(s), "l"(g) : "memory");
}
__device__ __forceinline__ void mma_tf32(float* c, const uint32_t* a, const uint32_t* b) {
    asm volatile(
        "mma.sync.aligned.m16n8k8.row.col.f32.tf32.tf32.f32 "
        "{%0,%1,%2,%3}, {%4,%5,%6,%7}, {%8,%9}, {%0,%1,%2,%3};"
        : "+f"(c[0]), "+f"(c[1]), "+f"(c[2]), "+f"(c[3])
        : "r"(a[0]), "r"(a[1]), "r"(a[2]), "r"(a[3]), "r"(b[0]), "r"(b[1]));
}

// ----------------------------------------------------------- prep rounding --
__global__ void __launch_bounds__(256) round_tf32(const float* __restrict__ in,
                                                  float* __restrict__ out, int n4) {
    int i = blockIdx.x * 256 + threadIdx.x;
    if (i < n4) {
        float4 v = ((const float4*)in)[i];
        v.x = tf32r(v.x); v.y = tf32r(v.y); v.z = tf32r(v.z); v.w = tf32r(v.w);
        ((float4*)out)[i] = v;
    }
}

// ------------------------------------------------------------ tf32 GEMM ----
template <int EPI>
__global__ void __launch_bounds__(128) gemm_mma(
    const float* __restrict__ Am, const float* __restrict__ Bw,
    const float* __restrict__ bias, const float* __restrict__ rel,
    float* __restrict__ Cout, const int N)
{
    constexpr int K = 768;
    constexpr int NC = K / 32;
    constexpr int ASTG = 128 * 36;
    constexpr int BSTG = 32 * 132;

    extern __shared__ float sh[];
    float* As = sh;
    float* Bs = sh + 2 * ASTG;

    const int tid  = threadIdx.x;
    const int wid  = tid >> 5;
    const int lane = tid & 31;
    const int g    = lane >> 2;
    const int tig  = lane & 3;
    const int wm   = (wid >> 1) * 64;
    const int wn   = (wid & 1) * 64;
    const int bx = blockIdx.x, by = blockIdx.y;

    const float* Ablk = Am + (size_t)by * 128 * K;
    const float* Bblk = Bw + bx * 128;
    const uint32_t sA = smem_u32(As);
    const uint32_t sB = smem_u32(Bs);

    auto issue = [&](int c, int s) {
        const float* Ag = Ablk + c * 32;
#pragma unroll
        for (int i = 0; i < 8; i++) {
            const int idx = i * 128 + tid;
            const int row = idx >> 3, c4 = idx & 7;
            cp16(sA + (uint32_t)(s * ASTG + row * 36 + c4 * 4) * 4,
                 Ag + (size_t)row * K + c4 * 4);
        }
        const float* Bg = Bblk + (size_t)c * 32 * N;
#pragma unroll
        for (int i = 0; i < 8; i++) {
            const int idx = i * 128 + tid;
            const int kr = idx >> 5, c4 = idx & 31;
            cp16(sB + (uint32_t)(s * BSTG + kr * 132 + c4 * 4) * 4,
                 Bg + (size_t)kr * N + c4 * 4);
        }
        asm volatile("cp.async.commit_group;" ::: "memory");
    };

    float acc[4][8][4];
#pragma unroll
    for (int mt = 0; mt < 4; mt++)
#pragma unroll
        for (int nt = 0; nt < 8; nt++)
#pragma unroll
            for (int r = 0; r < 4; r++) acc[mt][nt][r] = 0.0f;

    issue(0, 0);
    for (int c = 0; c < NC; c++) {
        const int s = c & 1;
        if (c + 1 < NC) {
            issue(c + 1, (c + 1) & 1);
            asm volatile("cp.async.wait_group 1;" ::: "memory");
        } else {
            asm volatile("cp.async.wait_group 0;" ::: "memory");
        }
        __syncthreads();

        const float* A0 = As + s * ASTG;
        const float* B0 = Bs + s * BSTG;
#pragma unroll
        for (int ks = 0; ks < 4; ks++) {
            uint32_t af[4][4];
#pragma unroll
            for (int mt = 0; mt < 4; mt++) {
                const float* ap = A0 + (wm + mt * 16 + g) * 36 + ks * 8 + tig;
                af[mt][0] = __float_as_uint(ap[0]);
                af[mt][1] = __float_as_uint(ap[8 * 36]);
                af[mt][2] = __float_as_uint(ap[4]);
                af[mt][3] = __float_as_uint(ap[8 * 36 + 4]);
            }
            uint32_t bf[8][2];
#pragma unroll
            for (int nt = 0; nt < 8; nt++) {
                const float* bp = B0 + (ks * 8 + tig) * 132 + wn + nt * 8 + g;
                bf[nt][0] = __float_as_uint(bp[0]);
                bf[nt][1] = __float_as_uint(bp[4 * 132]);
            }
#pragma unroll
            for (int mt = 0; mt < 4; mt++)
#pragma unroll
                for (int nt = 0; nt < 8; nt++)
                    mma_tf32(acc[mt][nt], af[mt], bf[nt]);
        }
        __syncthreads();
    }

    const int nb = bx * 128 + wn;
    const int mb = by * 128 + wm;
    if (EPI == 0) {
        const int which = (bx * 128) / 768;
        float* dst = (which == 0) ? g_q : (which == 1) ? g_k : g_v;
        const int bb = (by * 128) >> 10;
#pragma unroll
        for (int nt = 0; nt < 8; nt++) {
            const int n  = nb + nt * 8 + 2 * tig;
            const int nc = n - which * 768;
            const int hh = nc >> 6, dd = nc & 63;
            const float bv0 = bias[n], bv1 = bias[n + 1];
            const size_t hbase = (((size_t)(bb * 12 + hh)) << 10);
#pragma unroll
            for (int mt = 0; mt < 4; mt++) {
#pragma unroll
                for (int hr = 0; hr < 2; hr++) {
                    const int m = mb + mt * 16 + g + hr * 8;
                    const int t = m & 1023;
                    float v0 = acc[mt][nt][hr * 2 + 0] + bv0;
                    float v1 = acc[mt][nt][hr * 2 + 1] + bv1;
                    if (which == 0) { v0 *= 0.125f; v1 *= 0.125f; }
                    else if (which == 1 && t > 0) {
                        v0 += rel[(size_t)(t - 1) * 64 + dd];
                        v1 += rel[(size_t)(t - 1) * 64 + dd + 1];
                    }
                    float2 o; o.x = tf32r(v0); o.y = tf32r(v1);   // tf32 for flash mma
                    *(float2*)&dst[(hbase + t) * 64 + dd] = o;
                }
            }
        }
    } else {
#pragma unroll
        for (int nt = 0; nt < 8; nt++) {
            const int n = nb + nt * 8 + 2 * tig;
            const float bv0 = bias[n], bv1 = bias[n + 1];
#pragma unroll
            for (int mt = 0; mt < 4; mt++) {
#pragma unroll
                for (int hr = 0; hr < 2; hr++) {
                    const int m = mb + mt * 16 + g + hr * 8;
                    float2 o;
                    o.x = acc[mt][nt][hr * 2 + 0] + bv0;
                    o.y = acc[mt][nt][hr * 2 + 1] + bv1;
                    *(float2*)&Cout[(size_t)m * 768 + n] = o;
                }
            }
        }
    }
}

// ---------------------------------------------- tensor-core flash attention --
// 64 queries/block, 4 warps x 16 rows. K/V 64x64 tiles, cp.async double buffer.
// smem rows padded to 68 floats. S and PV via m16n8k8 tf32 mma.
#define TSZ 4352   // 64*68 floats per tile
__global__ void __launch_bounds__(128) flash_tc()
{
    extern __shared__ float fsh[];
    float* Qs = fsh;                 // [64][68]
    float* Ks = fsh + TSZ;           // [2][64][68]
    float* Vs = fsh + 3 * TSZ;       // [2][64][68]
    float* Ps = fsh + 5 * TSZ;       // [4 warps][16][68]

    const int qt  = (int)gridDim.x - 1 - (int)blockIdx.x;   // heavy blocks first
    const int bh  = blockIdx.y;
    const int tid = threadIdx.x;
    const int wid = tid >> 5;
    const int lane = tid & 31;
    const int g   = lane >> 2;
    const int tig = lane & 3;

    const float* qp = g_q + (size_t)bh * 65536;
    const float* kp = g_k + (size_t)bh * 65536;
    const float* vp = g_v + (size_t)bh * 65536;
    const int q0 = qt * 64;

    const uint32_t sQ = smem_u32(Qs);
    const uint32_t sK = smem_u32(Ks);
    const uint32_t sV = smem_u32(Vs);

    auto issueKV = [&](int kt, int s) {
        const float* kg = kp + (size_t)kt * 4096;
        const float* vg = vp + (size_t)kt * 4096;
        const uint32_t kd = sK + (uint32_t)s * TSZ * 4;
        const uint32_t vd = sV + (uint32_t)s * TSZ * 4;
#pragma unroll
        for (int i = 0; i < 8; i++) {
            const int idx = i * 128 + tid;
            const int row = idx >> 4, c4 = idx & 15;
            const uint32_t so = (uint32_t)(row * 68 + c4 * 4) * 4;
            cp16(kd + so, kg + row * 64 + c4 * 4);
            cp16(vd + so, vg + row * 64 + c4 * 4);
        }
        asm volatile("cp.async.commit_group;" ::: "memory");
    };

    // group 0: Q tile + KV stage 0
    {
        const float* qg = qp + (size_t)q0 * 64;
#pragma unroll
        for (int i = 0; i < 8; i++) {
            const int idx = i * 128 + tid;
            const int row = idx >> 4, c4 = idx & 15;
            cp16(sQ + (uint32_t)(row * 68 + c4 * 4) * 4, qg + row * 64 + c4 * 4);
        }
    }
    issueKV(0, 0);

    float Oacc[8][4];
#pragma unroll
    for (int d = 0; d < 8; d++)
#pragma unroll
        for (int r = 0; r < 4; r++) Oacc[d][r] = 0.0f;
    float mprev[2] = {-1e30f, -1e30f};
    float lsum[2]  = {0.0f, 0.0f};

    float* Psw = Ps + wid * 16 * 68;
    const int wq = wid * 16;

    for (int kt = 0; kt <= qt; kt++) {
        const int s = kt & 1;
        if (kt < qt) {
            issueKV(kt + 1, s ^ 1);
            asm volatile("cp.async.wait_group 1;" ::: "memory");
        } else {
            asm volatile("cp.async.wait_group 0;" ::: "memory");
        }
        __syncthreads();

        // ---- S = Q K^T ----
        float sacc[8][4];
#pragma unroll
        for (int nt = 0; nt < 8; nt++)
#pragma unroll
            for (int r = 0; r < 4; r++) sacc[nt][r] = 0.0f;

        const float* Kst = Ks + s * TSZ;
#pragma unroll
        for (int ks8 = 0; ks8 < 8; ks8++) {
            uint32_t a[4];
            const float* ap = Qs + (wq + g) * 68 + ks8 * 8 + tig;
            a[0] = __float_as_uint(ap[0]);
            a[1] = __float_as_uint(ap[8 * 68]);
            a[2] = __float_as_uint(ap[4]);
            a[3] = __float_as_uint(ap[8 * 68 + 4]);
#pragma unroll
            for (int nt = 0; nt < 8; nt++) {
                uint32_t b[2];
                const float* bp = Kst + (nt * 8 + g) * 68 + ks8 * 8 + tig;
                b[0] = __float_as_uint(bp[0]);
                b[1] = __float_as_uint(bp[4]);
                mma_tf32(sacc[nt], a, b);
            }
        }

        // ---- causal mask on diagonal tile ----
        if (kt == qt) {
#pragma unroll
            for (int nt = 0; nt < 8; nt++)
#pragma unroll
                for (int e = 0; e < 4; e++) {
                    const int row = wq + g + ((e >> 1) << 3);
                    const int col = nt * 8 + 2 * tig + (e & 1);
                    if (col > row) sacc[nt][e] = -1e30f;
                }
        }

        // ---- online softmax (rows g and g+8) ----
#pragma unroll
        for (int r = 0; r < 2; r++) {
            float mloc = -1e30f;
#pragma unroll
            for (int nt = 0; nt < 8; nt++)
                mloc = fmaxf(mloc, fmaxf(sacc[nt][2 * r], sacc[nt][2 * r + 1]));
            mloc = fmaxf(mloc, __shfl_xor_sync(0xffffffffu, mloc, 1));
            mloc = fmaxf(mloc, __shfl_xor_sync(0xffffffffu, mloc, 2));
            const float mnew = fmaxf(mprev[r], mloc);
            const float fac  = __expf(mprev[r] - mnew);
            float ls = 0.0f;
#pragma unroll
            for (int nt = 0; nt < 8; nt++) {
                float p0 = __expf(sacc[nt][2 * r]     - mnew);
                float p1 = __expf(sacc[nt][2 * r + 1] - mnew);
                ls += p0 + p1;
                float2 pv; pv.x = tf32r(p0); pv.y = tf32r(p1);
                *(float2*)&Psw[(g + r * 8) * 68 + nt * 8 + 2 * tig] = pv;
            }
            ls += __shfl_xor_sync(0xffffffffu, ls, 1);
            ls += __shfl_xor_sync(0xffffffffu, ls, 2);
            lsum[r] = lsum[r] * fac + ls;
            mprev[r] = mnew;
#pragma unroll
            for (int d = 0; d < 8; d++) {
                Oacc[d][2 * r]     *= fac;
                Oacc[d][2 * r + 1] *= fac;
            }
        }
        __syncwarp();

        // ---- O += P V ----
        const float* Vst = Vs + s * TSZ;
#pragma unroll
        for (int kc = 0; kc < 8; kc++) {
            uint32_t a[4];
            const float* ap = Psw + g * 68 + kc * 8 + tig;
            a[0] = __float_as_uint(ap[0]);
            a[1] = __float_as_uint(ap[8 * 68]);
            a[2] = __float_as_uint(ap[4]);
            a[3] = __float_as_uint(ap[8 * 68 + 4]);
#pragma unroll
            for (int dt = 0; dt < 8; dt++) {
                uint32_t b[2];
                const float* bp = Vst + (kc * 8 + tig) * 68 + dt * 8 + g;
                b[0] = __float_as_uint(bp[0]);
                b[1] = __float_as_uint(bp[4 * 68]);
                mma_tf32(Oacc[dt], a, b);
            }
        }
        __syncthreads();
    }

    // ---- epilogue: y[b][t][h*64+d] = O / l  (tf32-rounded for proj GEMM) ----
    const int bb = bh / 12;
    const int hh = bh - bb * 12;
#pragma unroll
    for (int r = 0; r < 2; r++) {
        const float inv = 1.0f / lsum[r];
        const int t = q0 + wq + g + r * 8;
        float* yrow = g_y + ((size_t)(bb * 1024 + t)) * 768 + hh * 64;
#pragma unroll
        for (int dt = 0; dt < 8; dt++) {
            float2 o;
            o.x = tf32r(Oacc[dt][2 * r]     * inv);
            o.y = tf32r(Oacc[dt][2 * r + 1] * inv);
            *(float2*)&yrow[dt * 8 + 2 * tig] = o;
        }
    }
}

// ---------------------------------------------------------------------------
extern "C" void kernel_launch(void* const* d_in, const int* in_sizes, int n_in,
                              void* d_out, int out_size)
{
    const float* x      = (const float*)d_in[0];
    const float* w_attn = (const float*)d_in[1];
    const float* b_attn = (const float*)d_in[2];
    const float* w_proj = (const float*)d_in[3];
    const float* b_proj = (const float*)d_in[4];
    const float* rel    = (const float*)d_in[5];
    float* out = (float*)d_out;
    (void)in_sizes; (void)n_in; (void)out_size;

    float *xr, *wr1, *wr2, *yp;
    cudaGetSymbolAddress((void**)&xr,  g_xr);
    cudaGetSymbolAddress((void**)&wr1, g_wr1);
    cudaGetSymbolAddress((void**)&wr2, g_wr2);
    cudaGetSymbolAddress((void**)&yp,  g_y);

    const int SMEM = (2 * 128 * 36 + 2 * 32 * 132) * 4;      // 70656 B
    const int FSMEM = 6 * TSZ * 4;                            // 104448 B
    cudaFuncSetAttribute(gemm_mma<0>, cudaFuncAttributeMaxDynamicSharedMemorySize, SMEM);
    cudaFuncSetAttribute(gemm_mma<1>, cudaFuncAttributeMaxDynamicSharedMemorySize, SMEM);
    cudaFuncSetAttribute(flash_tc,    cudaFuncAttributeMaxDynamicSharedMemorySize, FSMEM);

    round_tf32<<<ELEMS_BTC / 4 / 256, 256>>>(x, xr, ELEMS_BTC / 4);
    round_tf32<<<768 * 2304 / 4 / 256, 256>>>(w_attn, wr1, 768 * 2304 / 4);
    round_tf32<<<768 * 768 / 4 / 256, 256>>>(w_proj, wr2, 768 * 768 / 4);

    gemm_mma<0><<<dim3(18, 64), 128, SMEM>>>(xr, wr1, b_attn, rel, nullptr, 2304);

    flash_tc<<<dim3(16, 96), 128, FSMEM>>>();

    gemm_mma<1><<<dim3(6, 64), 128, SMEM>>>(yp, wr2, b_proj, nullptr, out, 768);
}

// round 10
// speedup vs baseline: 6.5131x; 2.0092x over previous
#include <cuda_runtime.h>
#include <cuda_fp16.h>
#include <cstdint>
#include <cstddef>

// B=8, T=1024, C=768, H=12, d=64 — full f16 storage, f32 accumulation.
//   prep:  f32 -> f16 convert of x, w_attn, w_proj
//   QKV :  m16n8k16 f16 mma -> scatter q/k/v (f16) (+bias, q*0.125, k+rel)
//   attn:  f16 flash (ldmatrix + HMMA), fp32 softmax
//   proj:  m16n8k16 f16 mma -> out (f32, +bias)

#define ELEMS_BHTD (8 * 12 * 1024 * 64)
#define ELEMS_BTC  (8 * 1024 * 768)

static __device__ __half g_qh[ELEMS_BHTD];
static __device__ __half g_kh[ELEMS_BHTD];
static __device__ __half g_vh[ELEMS_BHTD];
static __device__ __half g_yh[ELEMS_BTC];
static __device__ __half g_xh[ELEMS_BTC];
static __device__ __half g_wh1[768 * 2304];
static __device__ __half g_wh2[768 * 768];

// ---------------------------------------------------------------- helpers --
__device__ __forceinline__ uint32_t smem_u32(const void* p) {
    uint32_t a;
    asm("{ .reg .u64 t; cvta.to.shared.u64 t, %1; cvt.u32.u64 %0, t; }"
        : "=r"(a) : "l"(p));
    return a;
}
__device__ __forceinline__ void cp16(uint32_t s, const void* g) {
    asm volatile("cp.async.ca.shared.global [%0], [%1], 16;"
                 :: "r"(s), "l"(g) : "memory");
}
__device__ __forceinline__ void ldsm4(uint32_t* r, uint32_t a) {
    asm volatile("ldmatrix.sync.aligned.m8n8.x4.shared.b16 {%0,%1,%2,%3}, [%4];"
                 : "=r"(r[0]), "=r"(r[1]), "=r"(r[2]), "=r"(r[3]) : "r"(a));
}
__device__ __forceinline__ void ldsm4t(uint32_t* r, uint32_t a) {
    asm volatile("ldmatrix.sync.aligned.m8n8.x4.trans.shared.b16 {%0,%1,%2,%3}, [%4];"
                 : "=r"(r[0]), "=r"(r[1]), "=r"(r[2]), "=r"(r[3]) : "r"(a));
}
__device__ __forceinline__ void mma_f16(float* c, const uint32_t* a, const uint32_t* b) {
    asm volatile(
        "mma.sync.aligned.m16n8k16.row.col.f32.f16.f16.f32 "
        "{%0,%1,%2,%3}, {%4,%5,%6,%7}, {%8,%9}, {%0,%1,%2,%3};"
        : "+f"(c[0]), "+f"(c[1]), "+f"(c[2]), "+f"(c[3])
        : "r"(a[0]), "r"(a[1]), "r"(a[2]), "r"(a[3]), "r"(b[0]), "r"(b[1]));
}

// ----------------------------------------------------------- prep convert --
__global__ void __launch_bounds__(256) f2h(const float* __restrict__ in,
                                           __half* __restrict__ out, int n4) {
    int i = blockIdx.x * 256 + threadIdx.x;
    if (i < n4) {
        float4 v = ((const float4*)in)[i];
        __half2 h0 = __floats2half2_rn(v.x, v.y);
        __half2 h1 = __floats2half2_rn(v.z, v.w);
        uint2 u;
        u.x = *(uint32_t*)&h0;
        u.y = *(uint32_t*)&h1;
        ((uint2*)out)[i] = u;
    }
}

// ------------------------------------------------------------- f16 GEMM ----
// C[m,n] = A[m,:] . Bw[:,n] (+bias). A [M x 768] half, Bw [768 x N] half.
// 128x128 block tile, 4 warps of 64x64, BK=64 double-buffered cp.async.
// EPI 0: scatter q/k/v halves. EPI 1: float out.
template <int EPI>
__global__ void __launch_bounds__(128) gemm_h(
    const __half* __restrict__ Am, const __half* __restrict__ Bw,
    const float* __restrict__ bias, const float* __restrict__ rel,
    float* __restrict__ Cout, const int N)
{
    constexpr int K = 768;
    constexpr int NC = K / 64;          // 12 chunks
    constexpr int ASTG = 128 * 72;      // halves per A stage
    constexpr int BSTG = 64 * 136;      // halves per B stage

    extern __shared__ __half hsh[];
    __half* As = hsh;                   // [2][128][72]
    __half* Bs = hsh + 2 * ASTG;        // [2][64][136]

    const int tid  = threadIdx.x;
    const int wid  = tid >> 5;
    const int lane = tid & 31;
    const int g    = lane >> 2;
    const int tig  = lane & 3;
    const int wm   = (wid >> 1) * 64;
    const int wn   = (wid & 1) * 64;
    const int bx = blockIdx.x, by = blockIdx.y;

    const __half* Ablk = Am + (size_t)by * 128 * K;
    const __half* Bblk = Bw + bx * 128;
    const uint32_t sA = smem_u32(As);
    const uint32_t sB = smem_u32(Bs);

    // ldmatrix per-lane address components
    const int aRow  = lane & 15;        // + wm + mt*16
    const int aColH = 8 * (lane >> 4);  // + k
    const int bK    = (lane & 7) + 8 * ((lane >> 3) & 1);  // + k (trans)
    const int bN    = 8 * (lane >> 4);  // + wn + ntp*16

    auto issue = [&](int c, int s) {
        const __half* Ag = Ablk + c * 64;
#pragma unroll
        for (int i = 0; i < 8; i++) {
            const int idx = i * 128 + tid;
            const int row = idx >> 3, c8 = idx & 7;
            cp16(sA + (uint32_t)(s * ASTG + row * 72 + c8 * 8) * 2,
                 Ag + (size_t)row * K + c8 * 8);
        }
        const __half* Bg = Bblk + (size_t)c * 64 * N;
#pragma unroll
        for (int i = 0; i < 8; i++) {
            const int idx = i * 128 + tid;
            const int row = idx >> 4, c8 = idx & 15;
            cp16(sB + (uint32_t)(s * BSTG + row * 136 + c8 * 8) * 2,
                 Bg + (size_t)row * N + c8 * 8);
        }
        asm volatile("cp.async.commit_group;" ::: "memory");
    };

    float acc[4][8][4];
#pragma unroll
    for (int mt = 0; mt < 4; mt++)
#pragma unroll
        for (int nt = 0; nt < 8; nt++)
#pragma unroll
            for (int r = 0; r < 4; r++) acc[mt][nt][r] = 0.0f;

    issue(0, 0);
    for (int c = 0; c < NC; c++) {
        const int s = c & 1;
        if (c + 1 < NC) {
            issue(c + 1, s ^ 1);
            asm volatile("cp.async.wait_group 1;" ::: "memory");
        } else {
            asm volatile("cp.async.wait_group 0;" ::: "memory");
        }
        __syncthreads();

        const uint32_t A0 = sA + (uint32_t)(s * ASTG) * 2;
        const uint32_t B0 = sB + (uint32_t)(s * BSTG) * 2;
#pragma unroll
        for (int ks = 0; ks < 4; ks++) {
            const int kh = ks * 16;
            uint32_t af[4][4];
#pragma unroll
            for (int mt = 0; mt < 4; mt++)
                ldsm4(af[mt], A0 + (uint32_t)((wm + mt * 16 + aRow) * 72 + kh + aColH) * 2);
            uint32_t bf[8][2];
#pragma unroll
            for (int ntp = 0; ntp < 4; ntp++) {
                uint32_t t4[4];
                ldsm4t(t4, B0 + (uint32_t)((kh + bK) * 136 + wn + ntp * 16 + bN) * 2);
                bf[2 * ntp][0] = t4[0]; bf[2 * ntp][1] = t4[1];
                bf[2 * ntp + 1][0] = t4[2]; bf[2 * ntp + 1][1] = t4[3];
            }
#pragma unroll
            for (int mt = 0; mt < 4; mt++)
#pragma unroll
                for (int nt = 0; nt < 8; nt++)
                    mma_f16(acc[mt][nt], af[mt], bf[nt]);
        }
        __syncthreads();
    }

    // ---- epilogue: thread holds (g,2tig),(g,2tig+1),(g+8,...) of 8x8 tiles
    const int nb = bx * 128 + wn;
    const int mb = by * 128 + wm;
    if (EPI == 0) {
        const int which = (bx * 128) / 768;
        __half* dst = (which == 0) ? g_qh : (which == 1) ? g_kh : g_vh;
        const int bb = (by * 128) >> 10;
#pragma unroll
        for (int nt = 0; nt < 8; nt++) {
            const int n  = nb + nt * 8 + 2 * tig;
            const int nc = n - which * 768;
            const int hh = nc >> 6, dd = nc & 63;
            const float bv0 = bias[n], bv1 = bias[n + 1];
            const size_t hbase = (((size_t)(bb * 12 + hh)) << 10);
#pragma unroll
            for (int mt = 0; mt < 4; mt++) {
#pragma unroll
                for (int hr = 0; hr < 2; hr++) {
                    const int m = mb + mt * 16 + g + hr * 8;
                    const int t = m & 1023;
                    float v0 = acc[mt][nt][hr * 2 + 0] + bv0;
                    float v1 = acc[mt][nt][hr * 2 + 1] + bv1;
                    if (which == 0) { v0 *= 0.125f; v1 *= 0.125f; }
                    else if (which == 1 && t > 0) {
                        v0 += rel[(size_t)(t - 1) * 64 + dd];
                        v1 += rel[(size_t)(t - 1) * 64 + dd + 1];
                    }
                    *(__half2*)&dst[(hbase + t) * 64 + dd] = __floats2half2_rn(v0, v1);
                }
            }
        }
    } else {
#pragma unroll
        for (int nt = 0; nt < 8; nt++) {
            const int n = nb + nt * 8 + 2 * tig;
            const float bv0 = bias[n], bv1 = bias[n + 1];
#pragma unroll
            for (int mt = 0; mt < 4; mt++) {
#pragma unroll
                for (int hr = 0; hr < 2; hr++) {
                    const int m = mb + mt * 16 + g + hr * 8;
                    float2 o;
                    o.x = acc[mt][nt][hr * 2 + 0] + bv0;
                    o.y = acc[mt][nt][hr * 2 + 1] + bv1;
                    *(float2*)&Cout[(size_t)m * 768 + n] = o;
                }
            }
        }
    }
}

// ---------------------------------------------- f16 flash attention --------
// 64 queries/block, 4 warps x 16 rows. 64x64 K/V tiles double-buffered.
// All tiles half with row stride 72 (conflict-free ldmatrix).
#define QTS 4608   // 64*72 halves per tile
__global__ void __launch_bounds__(128) flash_h()
{
    extern __shared__ __half fsh[];
    __half* Qs = fsh;                  // [64][72]
    __half* Ks = fsh + QTS;            // [2][64][72]
    __half* Vs = fsh + 3 * QTS;        // [2][64][72]
    __half* Ps = fsh + 5 * QTS;        // [4][16][72]

    const int qt  = (int)gridDim.x - 1 - (int)blockIdx.x;   // heavy first
    const int bh  = blockIdx.y;
    const int tid = threadIdx.x;
    const int wid = tid >> 5;
    const int lane = tid & 31;
    const int g   = lane >> 2;
    const int tig = lane & 3;

    const __half* qp = g_qh + (size_t)bh * 65536;
    const __half* kp = g_kh + (size_t)bh * 65536;
    const __half* vp = g_vh + (size_t)bh * 65536;
    const int q0 = qt * 64;

    const uint32_t sQ = smem_u32(Qs);
    const uint32_t sK = smem_u32(Ks);
    const uint32_t sV = smem_u32(Vs);
    const uint32_t sP = smem_u32(Ps) + (uint32_t)(wid * 16 * 72) * 2;

    // ldmatrix lane addressing
    const int aRow  = lane & 15;
    const int aColH = 8 * (lane >> 4);
    const int kN    = 8 * ((lane >> 4) & 1) + (lane & 7);   // K n-row (non-trans)
    const int kKg   = 8 * ((lane >> 3) & 1);                // K k-group
    const int vK    = (lane & 7) + 8 * ((lane >> 3) & 1);   // V key-row (trans)
    const int vD    = 8 * (lane >> 4);                      // V d-offset

    auto issueKV = [&](int kt, int s) {
        const __half* kg = kp + (size_t)kt * 4096;
        const __half* vg = vp + (size_t)kt * 4096;
        const uint32_t kd = sK + (uint32_t)(s * QTS) * 2;
        const uint32_t vd = sV + (uint32_t)(s * QTS) * 2;
#pragma unroll
        for (int i = 0; i < 4; i++) {
            const int idx = i * 128 + tid;
            const int row = idx >> 3, c8 = idx & 7;
            const uint32_t so = (uint32_t)(row * 72 + c8 * 8) * 2;
            cp16(kd + so, kg + row * 64 + c8 * 8);
            cp16(vd + so, vg + row * 64 + c8 * 8);
        }
        asm volatile("cp.async.commit_group;" ::: "memory");
    };

    {
        const __half* qg = qp + (size_t)q0 * 64;
#pragma unroll
        for (int i = 0; i < 4; i++) {
            const int idx = i * 128 + tid;
            const int row = idx >> 3, c8 = idx & 7;
            cp16(sQ + (uint32_t)(row * 72 + c8 * 8) * 2, qg + row * 64 + c8 * 8);
        }
    }
    issueKV(0, 0);

    float Oacc[8][4];
#pragma unroll
    for (int d = 0; d < 8; d++)
#pragma unroll
        for (int r = 0; r < 4; r++) Oacc[d][r] = 0.0f;
    float mprev[2] = {-1e30f, -1e30f};
    float lsum[2]  = {0.0f, 0.0f};
    const int wq = wid * 16;

    for (int kt = 0; kt <= qt; kt++) {
        const int s = kt & 1;
        if (kt < qt) {
            issueKV(kt + 1, s ^ 1);
            asm volatile("cp.async.wait_group 1;" ::: "memory");
        } else {
            asm volatile("cp.async.wait_group 0;" ::: "memory");
        }
        __syncthreads();

        // ---- S = Q K^T : A=Q (non-trans), B=K[n][k] (non-trans) ----
        float sacc[8][4];
#pragma unroll
        for (int nt = 0; nt < 8; nt++)
#pragma unroll
            for (int r = 0; r < 4; r++) sacc[nt][r] = 0.0f;

        const uint32_t K0 = sK + (uint32_t)(s * QTS) * 2;
#pragma unroll
        for (int ks = 0; ks < 4; ks++) {
            const int kh = ks * 16;
            uint32_t a[4];
            ldsm4(a, sQ + (uint32_t)((wq + aRow) * 72 + kh + aColH) * 2);
#pragma unroll
            for (int ntp = 0; ntp < 4; ntp++) {
                uint32_t t4[4];
                ldsm4(t4, K0 + (uint32_t)((ntp * 16 + kN) * 72 + kh + kKg) * 2);
                mma_f16(sacc[2 * ntp],     a, t4);
                mma_f16(sacc[2 * ntp + 1], a, t4 + 2);
            }
        }

        // ---- causal mask on diagonal tile ----
        if (kt == qt) {
#pragma unroll
            for (int nt = 0; nt < 8; nt++)
#pragma unroll
                for (int e = 0; e < 4; e++) {
                    const int row = wq + g + ((e >> 1) << 3);
                    const int col = nt * 8 + 2 * tig + (e & 1);
                    if (col > row) sacc[nt][e] = -1e30f;
                }
        }

        // ---- online softmax ----
#pragma unroll
        for (int r = 0; r < 2; r++) {
            float mloc = -1e30f;
#pragma unroll
            for (int nt = 0; nt < 8; nt++)
                mloc = fmaxf(mloc, fmaxf(sacc[nt][2 * r], sacc[nt][2 * r + 1]));
            mloc = fmaxf(mloc, __shfl_xor_sync(0xffffffffu, mloc, 1));
            mloc = fmaxf(mloc, __shfl_xor_sync(0xffffffffu, mloc, 2));
            const float mnew = fmaxf(mprev[r], mloc);
            const float fac  = __expf(mprev[r] - mnew);
            float ls = 0.0f;
#pragma unroll
            for (int nt = 0; nt < 8; nt++) {
                float p0 = __expf(sacc[nt][2 * r]     - mnew);
                float p1 = __expf(sacc[nt][2 * r + 1] - mnew);
                ls += p0 + p1;
                *(__half2*)((char*)fsh + ((sP - smem_u32(fsh)) +
                    (uint32_t)((g + r * 8) * 72 + nt * 8 + 2 * tig) * 2)) =
                    __floats2half2_rn(p0, p1);
            }
            ls += __shfl_xor_sync(0xffffffffu, ls, 1);
            ls += __shfl_xor_sync(0xffffffffu, ls, 2);
            lsum[r] = lsum[r] * fac + ls;
            mprev[r] = mnew;
#pragma unroll
            for (int d = 0; d < 8; d++) {
                Oacc[d][2 * r]     *= fac;
                Oacc[d][2 * r + 1] *= fac;
            }
        }
        __syncwarp();

        // ---- O += P V : A=P (non-trans), B=V[k][d] (trans) ----
        const uint32_t V0 = sV + (uint32_t)(s * QTS) * 2;
#pragma unroll
        for (int kc = 0; kc < 4; kc++) {
            const int kh = kc * 16;
            uint32_t a[4];
            ldsm4(a, sP + (uint32_t)(aRow * 72 + kh + aColH) * 2);
#pragma unroll
            for (int dtp = 0; dtp < 4; dtp++) {
                uint32_t t4[4];
                ldsm4t(t4, V0 + (uint32_t)((kh + vK) * 72 + dtp * 16 + vD) * 2);
                mma_f16(Oacc[2 * dtp],     a, t4);
                mma_f16(Oacc[2 * dtp + 1], a, t4 + 2);
            }
        }
        __syncthreads();
    }

    // ---- epilogue: y (f16) = O / l ----
    const int bb = bh / 12;
    const int hh = bh - bb * 12;
#pragma unroll
    for (int r = 0; r < 2; r++) {
        const float inv = 1.0f / lsum[r];
        const int t = q0 + wq + g + r * 8;
        __half* yrow = g_yh + ((size_t)(bb * 1024 + t)) * 768 + hh * 64;
#pragma unroll
        for (int dt = 0; dt < 8; dt++) {
            *(__half2*)&yrow[dt * 8 + 2 * tig] =
                __floats2half2_rn(Oacc[dt][2 * r] * inv, Oacc[dt][2 * r + 1] * inv);
        }
    }
}

// ---------------------------------------------------------------------------
extern "C" void kernel_launch(void* const* d_in, const int* in_sizes, int n_in,
                              void* d_out, int out_size)
{
    const float* x      = (const float*)d_in[0];
    const float* w_attn = (const float*)d_in[1];
    const float* b_attn = (const float*)d_in[2];
    const float* w_proj = (const float*)d_in[3];
    const float* b_proj = (const float*)d_in[4];
    const float* rel    = (const float*)d_in[5];
    float* out = (float*)d_out;
    (void)in_sizes; (void)n_in; (void)out_size;

    __half *xh, *wh1, *wh2, *yh;
    cudaGetSymbolAddress((void**)&xh,  g_xh);
    cudaGetSymbolAddress((void**)&wh1, g_wh1);
    cudaGetSymbolAddress((void**)&wh2, g_wh2);
    cudaGetSymbolAddress((void**)&yh,  g_yh);

    const int GSMEM = (2 * 128 * 72 + 2 * 64 * 136) * 2;   // 71680 B
    const int FSMEM = 6 * QTS * 2;                          // 55296 B
    cudaFuncSetAttribute(gemm_h<0>, cudaFuncAttributeMaxDynamicSharedMemorySize, GSMEM);
    cudaFuncSetAttribute(gemm_h<1>, cudaFuncAttributeMaxDynamicSharedMemorySize, GSMEM);
    cudaFuncSetAttribute(flash_h,   cudaFuncAttributeMaxDynamicSharedMemorySize, FSMEM);

    f2h<<<ELEMS_BTC / 4 / 256, 256>>>(x, xh, ELEMS_BTC / 4);
    f2h<<<768 * 2304 / 4 / 256, 256>>>(w_attn, wh1, 768 * 2304 / 4);
    f2h<<<768 * 768 / 4 / 256, 256>>>(w_proj, wh2, 768 * 768 / 4);

    gemm_h<0><<<dim3(18, 64), 128, GSMEM>>>(xh, wh1, b_attn, rel, nullptr, 2304);

    flash_h<<<dim3(16, 96), 128, FSMEM>>>();

    gemm_h<1><<<dim3(6, 64), 128, GSMEM>>>(yh, wh2, b_proj, nullptr, out, 768);
}

// round 11
// speedup vs baseline: 7.0143x; 1.0770x over previous
#include <cuda_runtime.h>
#include <cuda_fp16.h>
#include <cstdint>
#include <cstddef>

// B=8, T=1024, C=768, H=12, d=64 — full f16 storage, f32 accumulation.
//   prep:  fused f32 -> f16 convert of x, w_attn, w_proj (one launch)
//   QKV :  m16n8k16 f16 mma, 256 thr / 8 warps (32x64 warp tiles) -> q/k/v f16
//   attn:  f16 flash (ldmatrix + HMMA), fp32 softmax
//   proj:  same gemm -> out (f32, +bias)

#define ELEMS_BHTD (8 * 12 * 1024 * 64)
#define ELEMS_BTC  (8 * 1024 * 768)
#define N4_X   (ELEMS_BTC / 4)
#define N4_W1  (768 * 2304 / 4)
#define N4_W2  (768 * 768 / 4)

static __device__ __half g_qh[ELEMS_BHTD];
static __device__ __half g_kh[ELEMS_BHTD];
static __device__ __half g_vh[ELEMS_BHTD];
static __device__ __half g_yh[ELEMS_BTC];
static __device__ __half g_xh[ELEMS_BTC];
static __device__ __half g_wh1[768 * 2304];
static __device__ __half g_wh2[768 * 768];

// ---------------------------------------------------------------- helpers --
__device__ __forceinline__ uint32_t smem_u32(const void* p) {
    uint32_t a;
    asm("{ .reg .u64 t; cvta.to.shared.u64 t, %1; cvt.u32.u64 %0, t; }"
        : "=r"(a) : "l"(p));
    return a;
}
__device__ __forceinline__ void cp16(uint32_t s, const void* g) {
    asm volatile("cp.async.ca.shared.global [%0], [%1], 16;"
                 :: "r"(s), "l"(g) : "memory");
}
__device__ __forceinline__ void ldsm4(uint32_t* r, uint32_t a) {
    asm volatile("ldmatrix.sync.aligned.m8n8.x4.shared.b16 {%0,%1,%2,%3}, [%4];"
                 : "=r"(r[0]), "=r"(r[1]), "=r"(r[2]), "=r"(r[3]) : "r"(a));
}
__device__ __forceinline__ void ldsm4t(uint32_t* r, uint32_t a) {
    asm volatile("ldmatrix.sync.aligned.m8n8.x4.trans.shared.b16 {%0,%1,%2,%3}, [%4];"
                 : "=r"(r[0]), "=r"(r[1]), "=r"(r[2]), "=r"(r[3]) : "r"(a));
}
__device__ __forceinline__ void mma_f16(float* c, const uint32_t* a, const uint32_t* b) {
    asm volatile(
        "mma.sync.aligned.m16n8k16.row.col.f32.f16.f16.f32 "
        "{%0,%1,%2,%3}, {%4,%5,%6,%7}, {%8,%9}, {%0,%1,%2,%3};"
        : "+f"(c[0]), "+f"(c[1]), "+f"(c[2]), "+f"(c[3])
        : "r"(a[0]), "r"(a[1]), "r"(a[2]), "r"(a[3]), "r"(b[0]), "r"(b[1]));
}

// ----------------------------------------------------------- fused prep ----
__global__ void __launch_bounds__(256) f2h_all(const float* __restrict__ x,
                                               const float* __restrict__ w1,
                                               const float* __restrict__ w2) {
    int i = blockIdx.x * 256 + threadIdx.x;
    const float* in;
    __half* out;
    if (i < N4_X)                { in = x;  out = g_xh; }
    else if (i < N4_X + N4_W1)   { in = w1; out = g_wh1; i -= N4_X; }
    else if (i < N4_X + N4_W1 + N4_W2) { in = w2; out = g_wh2; i -= N4_X + N4_W1; }
    else return;
    float4 v = ((const float4*)in)[i];
    __half2 h0 = __floats2half2_rn(v.x, v.y);
    __half2 h1 = __floats2half2_rn(v.z, v.w);
    uint2 u;
    u.x = *(uint32_t*)&h0;
    u.y = *(uint32_t*)&h1;
    ((uint2*)out)[i] = u;
}

// ------------------------------------------------------------- f16 GEMM ----
// C[m,n] = A[m,:] . Bw[:,n] (+bias). 128x128 block tile, 256 thr / 8 warps,
// warp tile 32x64 (warp grid 4 rows x 2 cols), BK=64 double-buffered cp.async.
// EPI 0: scatter q/k/v halves. EPI 1: float out.
template <int EPI>
__global__ void __launch_bounds__(256, 2) gemm_h(
    const __half* __restrict__ Am, const __half* __restrict__ Bw,
    const float* __restrict__ bias, const float* __restrict__ rel,
    float* __restrict__ Cout, const int N)
{
    constexpr int K = 768;
    constexpr int NC = K / 64;          // 12 chunks
    constexpr int ASTG = 128 * 72;      // halves per A stage
    constexpr int BSTG = 64 * 136;      // halves per B stage

    extern __shared__ __half hsh[];
    __half* As = hsh;                   // [2][128][72]
    __half* Bs = hsh + 2 * ASTG;        // [2][64][136]

    const int tid  = threadIdx.x;
    const int wid  = tid >> 5;
    const int lane = tid & 31;
    const int g    = lane >> 2;
    const int tig  = lane & 3;
    const int wm   = (wid >> 1) * 32;   // 4 warp rows
    const int wn   = (wid & 1) * 64;    // 2 warp cols
    const int bx = blockIdx.x, by = blockIdx.y;

    const __half* Ablk = Am + (size_t)by * 128 * K;
    const __half* Bblk = Bw + bx * 128;
    const uint32_t sA = smem_u32(As);
    const uint32_t sB = smem_u32(Bs);

    // ldmatrix per-lane address components
    const int aRow  = lane & 15;
    const int aColH = 8 * (lane >> 4);
    const int bK    = (lane & 7) + 8 * ((lane >> 3) & 1);
    const int bN    = 8 * (lane >> 4);

    auto issue = [&](int c, int s) {
        const __half* Ag = Ablk + c * 64;
#pragma unroll
        for (int i = 0; i < 4; i++) {
            const int idx = i * 256 + tid;
            const int row = idx >> 3, c8 = idx & 7;
            cp16(sA + (uint32_t)(s * ASTG + row * 72 + c8 * 8) * 2,
                 Ag + (size_t)row * K + c8 * 8);
        }
        const __half* Bg = Bblk + (size_t)c * 64 * N;
#pragma unroll
        for (int i = 0; i < 4; i++) {
            const int idx = i * 256 + tid;
            const int row = idx >> 4, c8 = idx & 15;
            cp16(sB + (uint32_t)(s * BSTG + row * 136 + c8 * 8) * 2,
                 Bg + (size_t)row * N + c8 * 8);
        }
        asm volatile("cp.async.commit_group;" ::: "memory");
    };

    float acc[2][8][4];
#pragma unroll
    for (int mt = 0; mt < 2; mt++)
#pragma unroll
        for (int nt = 0; nt < 8; nt++)
#pragma unroll
            for (int r = 0; r < 4; r++) acc[mt][nt][r] = 0.0f;

    issue(0, 0);
    for (int c = 0; c < NC; c++) {
        const int s = c & 1;
        if (c + 1 < NC) {
            issue(c + 1, s ^ 1);
            asm volatile("cp.async.wait_group 1;" ::: "memory");
        } else {
            asm volatile("cp.async.wait_group 0;" ::: "memory");
        }
        __syncthreads();

        const uint32_t A0 = sA + (uint32_t)(s * ASTG) * 2;
        const uint32_t B0 = sB + (uint32_t)(s * BSTG) * 2;
#pragma unroll
        for (int ks = 0; ks < 4; ks++) {
            const int kh = ks * 16;
            uint32_t af[2][4];
#pragma unroll
            for (int mt = 0; mt < 2; mt++)
                ldsm4(af[mt], A0 + (uint32_t)((wm + mt * 16 + aRow) * 72 + kh + aColH) * 2);
            uint32_t bf[8][2];
#pragma unroll
            for (int ntp = 0; ntp < 4; ntp++) {
                uint32_t t4[4];
                ldsm4t(t4, B0 + (uint32_t)((kh + bK) * 136 + wn + ntp * 16 + bN) * 2);
                bf[2 * ntp][0] = t4[0]; bf[2 * ntp][1] = t4[1];
                bf[2 * ntp + 1][0] = t4[2]; bf[2 * ntp + 1][1] = t4[3];
            }
#pragma unroll
            for (int mt = 0; mt < 2; mt++)
#pragma unroll
                for (int nt = 0; nt < 8; nt++)
                    mma_f16(acc[mt][nt], af[mt], bf[nt]);
        }
        __syncthreads();
    }

    // ---- epilogue ----
    const int nb = bx * 128 + wn;
    const int mb = by * 128 + wm;
    if (EPI == 0) {
        const int which = (bx * 128) / 768;
        __half* dst = (which == 0) ? g_qh : (which == 1) ? g_kh : g_vh;
        const int bb = (by * 128) >> 10;
#pragma unroll
        for (int nt = 0; nt < 8; nt++) {
            const int n  = nb + nt * 8 + 2 * tig;
            const int nc = n - which * 768;
            const int hh = nc >> 6, dd = nc & 63;
            const float bv0 = bias[n], bv1 = bias[n + 1];
            const size_t hbase = (((size_t)(bb * 12 + hh)) << 10);
#pragma unroll
            for (int mt = 0; mt < 2; mt++) {
#pragma unroll
                for (int hr = 0; hr < 2; hr++) {
                    const int m = mb + mt * 16 + g + hr * 8;
                    const int t = m & 1023;
                    float v0 = acc[mt][nt][hr * 2 + 0] + bv0;
                    float v1 = acc[mt][nt][hr * 2 + 1] + bv1;
                    if (which == 0) { v0 *= 0.125f; v1 *= 0.125f; }
                    else if (which == 1 && t > 0) {
                        v0 += rel[(size_t)(t - 1) * 64 + dd];
                        v1 += rel[(size_t)(t - 1) * 64 + dd + 1];
                    }
                    *(__half2*)&dst[(hbase + t) * 64 + dd] = __floats2half2_rn(v0, v1);
                }
            }
        }
    } else {
#pragma unroll
        for (int nt = 0; nt < 8; nt++) {
            const int n = nb + nt * 8 + 2 * tig;
            const float bv0 = bias[n], bv1 = bias[n + 1];
#pragma unroll
            for (int mt = 0; mt < 2; mt++) {
#pragma unroll
                for (int hr = 0; hr < 2; hr++) {
                    const int m = mb + mt * 16 + g + hr * 8;
                    float2 o;
                    o.x = acc[mt][nt][hr * 2 + 0] + bv0;
                    o.y = acc[mt][nt][hr * 2 + 1] + bv1;
                    *(float2*)&Cout[(size_t)m * 768 + n] = o;
                }
            }
        }
    }
}

// ---------------------------------------------- f16 flash attention --------
// 64 queries/block, 4 warps x 16 rows. 64x64 K/V tiles double-buffered.
#define QTS 4608   // 64*72 halves per tile
__global__ void __launch_bounds__(128) flash_h()
{
    extern __shared__ __half fsh[];
    __half* Qs = fsh;                  // [64][72]
    __half* Ks = fsh + QTS;            // [2][64][72]
    __half* Vs = fsh + 3 * QTS;        // [2][64][72]
    __half* Ps = fsh + 5 * QTS;        // [4][16][72]

    const int qt  = (int)gridDim.x - 1 - (int)blockIdx.x;   // heavy first
    const int bh  = blockIdx.y;
    const int tid = threadIdx.x;
    const int wid = tid >> 5;
    const int lane = tid & 31;
    const int g   = lane >> 2;
    const int tig = lane & 3;

    const __half* qp = g_qh + (size_t)bh * 65536;
    const __half* kp = g_kh + (size_t)bh * 65536;
    const __half* vp = g_vh + (size_t)bh * 65536;
    const int q0 = qt * 64;

    const uint32_t sQ = smem_u32(Qs);
    const uint32_t sK = smem_u32(Ks);
    const uint32_t sV = smem_u32(Vs);
    const uint32_t sP = smem_u32(Ps) + (uint32_t)(wid * 16 * 72) * 2;

    const int aRow  = lane & 15;
    const int aColH = 8 * (lane >> 4);
    const int kN    = 8 * ((lane >> 4) & 1) + (lane & 7);
    const int kKg   = 8 * ((lane >> 3) & 1);
    const int vK    = (lane & 7) + 8 * ((lane >> 3) & 1);
    const int vD    = 8 * (lane >> 4);

    auto issueKV = [&](int kt, int s) {
        const __half* kg = kp + (size_t)kt * 4096;
        const __half* vg = vp + (size_t)kt * 4096;
        const uint32_t kd = sK + (uint32_t)(s * QTS) * 2;
        const uint32_t vd = sV + (uint32_t)(s * QTS) * 2;
#pragma unroll
        for (int i = 0; i < 4; i++) {
            const int idx = i * 128 + tid;
            const int row = idx >> 3, c8 = idx & 7;
            const uint32_t so = (uint32_t)(row * 72 + c8 * 8) * 2;
            cp16(kd + so, kg + row * 64 + c8 * 8);
            cp16(vd + so, vg + row * 64 + c8 * 8);
        }
        asm volatile("cp.async.commit_group;" ::: "memory");
    };

    {
        const __half* qg = qp + (size_t)q0 * 64;
#pragma unroll
        for (int i = 0; i < 4; i++) {
            const int idx = i * 128 + tid;
            const int row = idx >> 3, c8 = idx & 7;
            cp16(sQ + (uint32_t)(row * 72 + c8 * 8) * 2, qg + row * 64 + c8 * 8);
        }
    }
    issueKV(0, 0);

    float Oacc[8][4];
#pragma unroll
    for (int d = 0; d < 8; d++)
#pragma unroll
        for (int r = 0; r < 4; r++) Oacc[d][r] = 0.0f;
    float mprev[2] = {-1e30f, -1e30f};
    float lsum[2]  = {0.0f, 0.0f};
    const int wq = wid * 16;

    for (int kt = 0; kt <= qt; kt++) {
        const int s = kt & 1;
        if (kt < qt) {
            issueKV(kt + 1, s ^ 1);
            asm volatile("cp.async.wait_group 1;" ::: "memory");
        } else {
            asm volatile("cp.async.wait_group 0;" ::: "memory");
        }
        __syncthreads();

        // ---- S = Q K^T ----
        float sacc[8][4];
#pragma unroll
        for (int nt = 0; nt < 8; nt++)
#pragma unroll
            for (int r = 0; r < 4; r++) sacc[nt][r] = 0.0f;

        const uint32_t K0 = sK + (uint32_t)(s * QTS) * 2;
#pragma unroll
        for (int ks = 0; ks < 4; ks++) {
            const int kh = ks * 16;
            uint32_t a[4];
            ldsm4(a, sQ + (uint32_t)((wq + aRow) * 72 + kh + aColH) * 2);
#pragma unroll
            for (int ntp = 0; ntp < 4; ntp++) {
                uint32_t t4[4];
                ldsm4(t4, K0 + (uint32_t)((ntp * 16 + kN) * 72 + kh + kKg) * 2);
                mma_f16(sacc[2 * ntp],     a, t4);
                mma_f16(sacc[2 * ntp + 1], a, t4 + 2);
            }
        }

        // ---- causal mask on diagonal tile ----
        if (kt == qt) {
#pragma unroll
            for (int nt = 0; nt < 8; nt++)
#pragma unroll
                for (int e = 0; e < 4; e++) {
                    const int row = wq + g + ((e >> 1) << 3);
                    const int col = nt * 8 + 2 * tig + (e & 1);
                    if (col > row) sacc[nt][e] = -1e30f;
                }
        }

        // ---- online softmax ----
#pragma unroll
        for (int r = 0; r < 2; r++) {
            float mloc = -1e30f;
#pragma unroll
            for (int nt = 0; nt < 8; nt++)
                mloc = fmaxf(mloc, fmaxf(sacc[nt][2 * r], sacc[nt][2 * r + 1]));
            mloc = fmaxf(mloc, __shfl_xor_sync(0xffffffffu, mloc, 1));
            mloc = fmaxf(mloc, __shfl_xor_sync(0xffffffffu, mloc, 2));
            const float mnew = fmaxf(mprev[r], mloc);
            const float fac  = __expf(mprev[r] - mnew);
            float ls = 0.0f;
#pragma unroll
            for (int nt = 0; nt < 8; nt++) {
                float p0 = __expf(sacc[nt][2 * r]     - mnew);
                float p1 = __expf(sacc[nt][2 * r + 1] - mnew);
                ls += p0 + p1;
                *(__half2*)((char*)fsh + ((sP - smem_u32(fsh)) +
                    (uint32_t)((g + r * 8) * 72 + nt * 8 + 2 * tig) * 2)) =
                    __floats2half2_rn(p0, p1);
            }
            ls += __shfl_xor_sync(0xffffffffu, ls, 1);
            ls += __shfl_xor_sync(0xffffffffu, ls, 2);
            lsum[r] = lsum[r] * fac + ls;
            mprev[r] = mnew;
#pragma unroll
            for (int d = 0; d < 8; d++) {
                Oacc[d][2 * r]     *= fac;
                Oacc[d][2 * r + 1] *= fac;
            }
        }
        __syncwarp();

        // ---- O += P V ----
        const uint32_t V0 = sV + (uint32_t)(s * QTS) * 2;
#pragma unroll
        for (int kc = 0; kc < 4; kc++) {
            const int kh = kc * 16;
            uint32_t a[4];
            ldsm4(a, sP + (uint32_t)(aRow * 72 + kh + aColH) * 2);
#pragma unroll
            for (int dtp = 0; dtp < 4; dtp++) {
                uint32_t t4[4];
                ldsm4t(t4, V0 + (uint32_t)((kh + vK) * 72 + dtp * 16 + vD) * 2);
                mma_f16(Oacc[2 * dtp],     a, t4);
                mma_f16(Oacc[2 * dtp + 1], a, t4 + 2);
            }
        }
        __syncthreads();
    }

    // ---- epilogue ----
    const int bb = bh / 12;
    const int hh = bh - bb * 12;
#pragma unroll
    for (int r = 0; r < 2; r++) {
        const float inv = 1.0f / lsum[r];
        const int t = q0 + wq + g + r * 8;
        __half* yrow = g_yh + ((size_t)(bb * 1024 + t)) * 768 + hh * 64;
#pragma unroll
        for (int dt = 0; dt < 8; dt++) {
            *(__half2*)&yrow[dt * 8 + 2 * tig] =
                __floats2half2_rn(Oacc[dt][2 * r] * inv, Oacc[dt][2 * r + 1] * inv);
        }
    }
}

// ---------------------------------------------------------------------------
extern "C" void kernel_launch(void* const* d_in, const int* in_sizes, int n_in,
                              void* d_out, int out_size)
{
    const float* x      = (const float*)d_in[0];
    const float* w_attn = (const float*)d_in[1];
    const float* b_attn = (const float*)d_in[2];
    const float* w_proj = (const float*)d_in[3];
    const float* b_proj = (const float*)d_in[4];
    const float* rel    = (const float*)d_in[5];
    float* out = (float*)d_out;
    (void)in_sizes; (void)n_in; (void)out_size;

    __half *xh, *wh1, *wh2, *yh;
    cudaGetSymbolAddress((void**)&xh,  g_xh);
    cudaGetSymbolAddress((void**)&wh1, g_wh1);
    cudaGetSymbolAddress((void**)&wh2, g_wh2);
    cudaGetSymbolAddress((void**)&yh,  g_yh);

    const int GSMEM = (2 * 128 * 72 + 2 * 64 * 136) * 2;   // 71680 B
    const int FSMEM = 6 * QTS * 2;                          // 55296 B
    cudaFuncSetAttribute(gemm_h<0>, cudaFuncAttributeMaxDynamicSharedMemorySize, GSMEM);
    cudaFuncSetAttribute(gemm_h<1>, cudaFuncAttributeMaxDynamicSharedMemorySize, GSMEM);
    cudaFuncSetAttribute(flash_h,   cudaFuncAttributeMaxDynamicSharedMemorySize, FSMEM);

    // fused prep: one launch converts x, w_attn, w_proj to f16
    const int TOT4 = N4_X + N4_W1 + N4_W2;
    f2h_all<<<(TOT4 + 255) / 256, 256>>>(x, w_attn, w_proj);

    gemm_h<0><<<dim3(18, 64), 256, GSMEM>>>(xh, wh1, b_attn, rel, nullptr, 2304);

    flash_h<<<dim3(16, 96), 128, FSMEM>>>();

    gemm_h<1><<<dim3(6, 64), 256, GSMEM>>>(yh, wh2, b_proj, nullptr, out, 768);
}